// round 1
// baseline (speedup 1.0000x reference)
#include <cuda_runtime.h>

// Problem constants
#define PP      128      // polygons
#define NN      128      // pred points per polygon per level
#define MM      1024     // gt points per polygon
#define CHUNKS  4
#define CM      (MM/CHUNKS)   // 256 gt points per chunk
#define NPTS    (3*PP*NN)     // 49152 total pred points
#define NB2     48            // combine-kernel blocks

// level weights / (3 * P * N)
#define W0 (0.2f/49152.0f)
#define W1 (0.3f/49152.0f)
#define W2 (0.5f/49152.0f)

typedef unsigned long long u64;

// Scratch (no allocations allowed): partial min-d2 per chunk, block sums
__device__ float g_partial[CHUNKS][NPTS];
__device__ float g_bsum[NB2];

// ---- packed f32x2 helpers (sm_103a) ----
__device__ __forceinline__ u64 pack2(float x) {
    u64 r;
    asm("mov.b64 %0, {%1, %1};" : "=l"(r) : "f"(x));
    return r;
}
__device__ __forceinline__ u64 fma2(u64 a, u64 b, u64 c) {
    u64 d;
    asm("fma.rn.f32x2 %0, %1, %2, %3;" : "=l"(d) : "l"(a), "l"(b), "l"(c));
    return d;
}
__device__ __forceinline__ void unpack2(u64 v, float& lo, float& hi) {
    asm("mov.b64 {%0, %1}, %2;" : "=f"(lo), "=f"(hi) : "l"(v));
}

// Kernel 1: per (chunk, polygon) partial min of t = |g|^2 - 2 p.g over 256 gt
// points, for all 3 levels of point n = tid. Writes partial min-d2.
__global__ __launch_bounds__(128) void k_partial(
    const float* __restrict__ pred0, const float* __restrict__ pred1,
    const float* __restrict__ pred2, const float* __restrict__ gt)
{
    __shared__ __align__(16) float sA[CM];
    __shared__ __align__(16) float sB[CM];
    __shared__ __align__(16) float sC[CM];

    const int chunk = blockIdx.x;
    const int p     = blockIdx.y;
    const int tid   = threadIdx.x;

    // Load this chunk's gt points, precompute A=-2gx, B=-2gy, C=|g|^2
    const float2* gsrc = (const float2*)(gt + ((size_t)p * MM + (size_t)chunk * CM) * 2);
    #pragma unroll
    for (int i = 0; i < CM / 128; i++) {
        int m = tid + i * 128;
        float2 g = gsrc[m];
        sA[m] = -2.0f * g.x;
        sB[m] = -2.0f * g.y;
        sC[m] = fmaf(g.x, g.x, g.y * g.y);
    }

    // This thread's 3 points (same n across levels); coords are [...,1:] of last dim 3
    const int base = (p * NN + tid) * 3;
    const float x0 = pred0[base + 1], y0 = pred0[base + 2];
    const float x1 = pred1[base + 1], y1 = pred1[base + 2];
    const float x2 = pred2[base + 1], y2 = pred2[base + 2];
    __syncthreads();

    const u64 X0 = pack2(x0), Y0 = pack2(y0);
    const u64 X1 = pack2(x1), Y1 = pack2(y1);
    const u64 X2 = pack2(x2), Y2 = pack2(y2);

    const u64* A2 = (const u64*)sA;
    const u64* B2 = (const u64*)sB;
    const u64* C2 = (const u64*)sC;

    const float INF = __int_as_float(0x7f800000);
    float m0l = INF, m0h = INF, m1l = INF, m1h = INF, m2l = INF, m2h = INF;

    #pragma unroll 4
    for (int i = 0; i < CM / 2; i++) {
        u64 a = A2[i], b = B2[i], c = C2[i];   // 3x LDS.64, warp-broadcast
        u64 t0 = fma2(Y0, b, fma2(X0, a, c));  // t = C + A*px + B*py (2 cands packed)
        u64 t1 = fma2(Y1, b, fma2(X1, a, c));
        u64 t2 = fma2(Y2, b, fma2(X2, a, c));
        float lo, hi;
        unpack2(t0, lo, hi); m0l = fminf(m0l, lo); m0h = fminf(m0h, hi);
        unpack2(t1, lo, hi); m1l = fminf(m1l, lo); m1h = fminf(m1h, hi);
        unpack2(t2, lo, hi); m2l = fminf(m2l, lo); m2h = fminf(m2h, hi);
    }

    const int pt = p * NN + tid;
    g_partial[chunk][0 * (PP * NN) + pt] = fminf(m0l, m0h) + fmaf(x0, x0, y0 * y0);
    g_partial[chunk][1 * (PP * NN) + pt] = fminf(m1l, m1h) + fmaf(x1, x1, y1 * y1);
    g_partial[chunk][2 * (PP * NN) + pt] = fminf(m2l, m2h) + fmaf(x2, x2, y2 * y2);
}

// Kernel 2: min over chunks, sqrt, weight, block-reduce. 48 blocks x 256 thr x 4 pts.
__global__ __launch_bounds__(256) void k_combine()
{
    __shared__ float red[256];
    const int j0 = blockIdx.x * 1024 + threadIdx.x;
    float s = 0.0f;
    #pragma unroll
    for (int k = 0; k < 4; k++) {
        int j = j0 + k * 256;
        float v = g_partial[0][j];
        v = fminf(v, g_partial[1][j]);
        v = fminf(v, g_partial[2][j]);
        v = fminf(v, g_partial[3][j]);
        float d = sqrtf(fmaxf(v, 0.0f));
        int level = j >> 14;                 // j / 16384
        float w = (level == 0) ? W0 : ((level == 1) ? W1 : W2);
        s = fmaf(w, d, s);
    }
    red[threadIdx.x] = s;
    __syncthreads();
    #pragma unroll
    for (int off = 128; off > 0; off >>= 1) {
        if (threadIdx.x < off) red[threadIdx.x] += red[threadIdx.x + off];
        __syncthreads();
    }
    if (threadIdx.x == 0) g_bsum[blockIdx.x] = red[0];
}

// Kernel 3: deterministic final sum of 48 block partials.
__global__ void k_final(float* __restrict__ out)
{
    float s = 0.0f;
    #pragma unroll
    for (int i = 0; i < NB2; i++) s += g_bsum[i];
    *out = s;
}

extern "C" void kernel_launch(void* const* d_in, const int* in_sizes, int n_in,
                              void* d_out, int out_size)
{
    const float* pred0 = (const float*)d_in[0];
    const float* pred1 = (const float*)d_in[1];
    const float* pred2 = (const float*)d_in[2];
    const float* gt    = (const float*)d_in[3];

    dim3 grid1(CHUNKS, PP);
    k_partial<<<grid1, 128>>>(pred0, pred1, pred2, gt);
    k_combine<<<NB2, 256>>>();
    k_final<<<1, 1>>>((float*)d_out);
}